// round 1
// baseline (speedup 1.0000x reference)
#include <cuda_runtime.h>

// Problem constants (fixed shapes for this problem)
#define BB 256
#define TT 4096
#define CIN0 16
#define HH 20
#define GG 60   // 3*H

// Scratch (device globals; no allocation allowed in kernel_launch)
__device__ float g_gx[(size_t)BB * TT * GG];    // reused: gx0 for layer0, then gx1 for layer1
__device__ float g_hseq[(size_t)BB * TT * HH];  // layer-0 output sequence

__device__ __forceinline__ float sigmoidf_(float x) {
    return __fdividef(1.0f, 1.0f + __expf(-x));
}
__device__ __forceinline__ float tanhf_(float x) {
    // tanh(x) = 2*sigmoid(2x) - 1 ; abs err ~1e-7, fine for 1e-3 tolerance
    return __fdividef(2.0f, 1.0f + __expf(-2.0f * x)) - 1.0f;
}

// ---------------------------------------------------------------------------
// gx kernel: out[bt, g] = bias[g] + sum_c in[bt, c] * W[g, c]
// blockDim = (64, 4): 4 timestep-rows per block, 64 threads over g (60 active)
// SRC_HSEQ selects reading from g_hseq (layer-1 input) vs. the x pointer.
// Always writes g_gx.
// ---------------------------------------------------------------------------
template<int CIN, bool SRC_HSEQ>
__global__ void gx_kernel(const float* __restrict__ xin,
                          const float* __restrict__ W,
                          const float* __restrict__ bias) {
    __shared__ float xs[4][CIN];
    const float* in = SRC_HSEQ ? g_hseq : xin;
    size_t bt = (size_t)blockIdx.x * 4 + threadIdx.y;
    if (threadIdx.x < CIN)
        xs[threadIdx.y][threadIdx.x] = in[bt * CIN + threadIdx.x];
    __syncthreads();
    int g = threadIdx.x;
    if (g < GG) {
        float acc = bias[g];
#pragma unroll
        for (int c = 0; c < CIN; ++c)
            acc += xs[threadIdx.y][c] * W[g * CIN + c];
        g_gx[bt * GG + g] = acc;
    }
}

// ---------------------------------------------------------------------------
// Recurrent GRU layer: one warp per batch element. Lane i<20 owns hidden
// unit i and keeps all three W_hh rows (r,z,n) for that unit in registers.
// h[j] is broadcast via shuffles. gx for step t+1 is double-buffered in regs.
// FINAL=false: writes h sequence to g_hseq. FINAL=true: fuses o = h.Wo + bo.
// Both write their final h into the h_n region of d_out.
// ---------------------------------------------------------------------------
template<bool FINAL>
__global__ void __launch_bounds__(32)
gru_rec_kernel(const float* __restrict__ W_hh,
               const float* __restrict__ b_hh,
               const float* __restrict__ h0,    // [B,2,H]
               int layer,
               const float* __restrict__ W_o,   // [1,H] (may be null)
               const float* __restrict__ b_o,   // [1]   (may be null)
               float* __restrict__ out)         // d_out: o[B*T] then h_n[B,2,H]
{
    const int b = blockIdx.x;
    const int i = threadIdx.x;
    if (i >= HH) return;
    const unsigned MASK = 0x000FFFFFu;

    // Load this unit's recurrent weights into registers (amortized over T=4096)
    float whr[HH], whz[HH], whn[HH];
#pragma unroll
    for (int j = 0; j < HH; ++j) {
        whr[j] = W_hh[(0 * HH + i) * HH + j];
        whz[j] = W_hh[(1 * HH + i) * HH + j];
        whn[j] = W_hh[(2 * HH + i) * HH + j];
    }
    const float bhr = b_hh[i], bhz = b_hh[HH + i], bhn = b_hh[2 * HH + i];

    float h = h0[(b * 2 + layer) * HH + i];
    const float wo = FINAL ? W_o[i] : 0.0f;
    const float bo = FINAL ? b_o[0] : 0.0f;

    const float* gxp = g_gx + (size_t)b * TT * GG;

    // Prime the gx double buffer
    float pr = gxp[i], pz = gxp[HH + i], pn = gxp[2 * HH + i];

    for (int t = 0; t < TT; ++t) {
        const float gr = pr, gz = pz, gn = pn;
        // Prefetch next step's gx (independent of h -> off the critical chain)
        const int tn = (t + 1 < TT) ? (t + 1) : t;
        const float* nx = gxp + (size_t)tn * GG;
        pr = nx[i]; pz = nx[HH + i]; pn = nx[2 * HH + i];

        // gh = W_hh . h  (2 accumulators per gate to halve FMA chain depth)
        float ar0 = bhr, az0 = bhz, an0 = bhn;
        float ar1 = 0.f, az1 = 0.f, an1 = 0.f;
#pragma unroll
        for (int j = 0; j < HH; j += 2) {
            const float hj0 = __shfl_sync(MASK, h, j);
            const float hj1 = __shfl_sync(MASK, h, j + 1);
            ar0 += whr[j] * hj0;     ar1 += whr[j + 1] * hj1;
            az0 += whz[j] * hj0;     az1 += whz[j + 1] * hj1;
            an0 += whn[j] * hj0;     an1 += whn[j + 1] * hj1;
        }

        const float r = sigmoidf_(gr + ar0 + ar1);
        const float z = sigmoidf_(gz + az0 + az1);
        const float n = tanhf_(gn + r * (an0 + an1));
        h = n + z * (h - n);

        if (!FINAL) {
            g_hseq[((size_t)b * TT + t) * HH + i] = h;
        } else {
            // o[b,t] = sum_i h_i * wo_i + bo  (warp reduce over 20 lanes)
            float v = h * wo;
            {
                float u = __shfl_down_sync(MASK, v, 16);
                if (i < 4) v += u;                 // lanes 0..3 fold in 16..19
                v += __shfl_down_sync(MASK, v, 8); // lanes 0..7 valid after
                v += __shfl_down_sync(MASK, v, 4); // lanes 0..3 valid
                v += __shfl_down_sync(MASK, v, 2);
                v += __shfl_down_sync(MASK, v, 1); // lane 0 = full sum
            }
            if (i == 0) out[(size_t)b * TT + t] = v + bo;
        }
    }

    // h_n[b, layer, i]
    out[(size_t)BB * TT + (b * 2 + layer) * HH + i] = h;
}

// ---------------------------------------------------------------------------
// kernel_launch
// inputs (metadata order):
//  0:x [B,T,C]  1:h0 [B,2,H]
//  2:W_ih0 [3H,C] 3:W_hh0 [3H,H] 4:b_ih0 [3H] 5:b_hh0 [3H]
//  6:W_ih1 [3H,H] 7:W_hh1 [3H,H] 8:b_ih1 [3H] 9:b_hh1 [3H]
//  10:W_o [1,H] 11:b_o [1]
// out: o [B*T] floats followed by h_n [B,2,H] floats
// ---------------------------------------------------------------------------
extern "C" void kernel_launch(void* const* d_in, const int* in_sizes, int n_in,
                              void* d_out, int out_size) {
    const float* x     = (const float*)d_in[0];
    const float* h0    = (const float*)d_in[1];
    const float* W_ih0 = (const float*)d_in[2];
    const float* W_hh0 = (const float*)d_in[3];
    const float* b_ih0 = (const float*)d_in[4];
    const float* b_hh0 = (const float*)d_in[5];
    const float* W_ih1 = (const float*)d_in[6];
    const float* W_hh1 = (const float*)d_in[7];
    const float* b_ih1 = (const float*)d_in[8];
    const float* b_hh1 = (const float*)d_in[9];
    const float* W_o   = (const float*)d_in[10];
    const float* b_o   = (const float*)d_in[11];
    float* out = (float*)d_out;

    const dim3 gx_block(64, 4);
    const int gx_grid = (BB * TT) / 4;

    // Phase 1: gx0 = x . W_ih0^T + b_ih0
    gx_kernel<CIN0, false><<<gx_grid, gx_block>>>(x, W_ih0, b_ih0);
    // Phase 2: layer-0 recurrence -> g_hseq, hn0
    gru_rec_kernel<false><<<BB, 32>>>(W_hh0, b_hh0, h0, 0, nullptr, nullptr, out);
    // Phase 3: gx1 = h_out0 . W_ih1^T + b_ih1 (reuses g_gx)
    gx_kernel<HH, true><<<gx_grid, gx_block>>>(nullptr, W_ih1, b_ih1);
    // Phase 4: layer-1 recurrence + fused output head -> o, hn1
    gru_rec_kernel<true><<<BB, 32>>>(W_hh1, b_hh1, h0, 1, W_o, b_o, out);
}

// round 2
// speedup vs baseline: 4.1196x; 4.1196x over previous
#include <cuda_runtime.h>

// Fixed problem shape
#define BB 256
#define TT 4096
#define CC 16
#define HH 20
#define GG 60          // 3*H
#define CHUNK 32
#define NCHUNK (TT / CHUNK)   // 128

__device__ __forceinline__ float sigf(float x) {
    return __fdividef(1.0f, 1.0f + __expf(-x));
}
__device__ __forceinline__ float tanhf_(float x) {
    return __fdividef(2.0f, 1.0f + __expf(-2.0f * x)) - 1.0f;
}

// ---------------------------------------------------------------------------
// Fully fused 2-layer GRU + output head. One block per batch element.
// 5 warps/block form a per-timestep software pipeline (1 barrier per step):
//   w4: DMA x chunks (32 steps) into smem ring, 1 chunk ahead-of-use by 32 steps
//   w1: gx0[t]  = W_ih0 . x[t] + b_ih0
//   w0: h0[t-1] = GRUcell(gx0[t-1], h0[t-2])        (lag 1)
//   w2: gx1[t-2]= W_ih1 . h0[t-2] + b_ih1           (lag 2)
//   w3: h1[t-3] = GRUcell(gx1[t-3], h1[t-4]); o[t-3] (lag 3)
// All inter-warp data flows through 4-deep smem rings; the per-step
// __syncthreads() provides the ordering (BAR drains pending STS on sm_103a).
// ---------------------------------------------------------------------------
__global__ void __launch_bounds__(160)
fused_gru_kernel(const float* __restrict__ x,      // [B,T,C]
                 const float* __restrict__ h0in,   // [B,2,H]
                 const float* __restrict__ W_ih0, const float* __restrict__ W_hh0,
                 const float* __restrict__ b_ih0, const float* __restrict__ b_hh0,
                 const float* __restrict__ W_ih1, const float* __restrict__ W_hh1,
                 const float* __restrict__ b_ih1, const float* __restrict__ b_hh1,
                 const float* __restrict__ W_o,   const float* __restrict__ b_o,
                 float* __restrict__ out)          // o[B*T] then h_n[B,2,H]
{
    const int b   = blockIdx.x;
    const int tid = threadIdx.x;
    const int w   = tid >> 5;
    const int i   = tid & 31;
    const unsigned MASK = 0x000FFFFFu;

    __shared__ float s_x[4][CHUNK][CC];   // x chunk ring (8 KB)
    __shared__ float s_gx0[4][GG];
    __shared__ float s_h0[4][HH];
    __shared__ float s_gx1[4][GG];
    __shared__ float s_h1[4][HH];

    const float* xb = x + (size_t)b * TT * CC;

    // ---- per-role register state -------------------------------------------
    float wreg[GG];
    float br = 0.f, bz = 0.f, bn = 0.f;
    float hprev = 0.f, wo = 0.f, bo = 0.f;

    if (w == 0 && i < HH) {                       // layer-0 recurrent weights
#pragma unroll
        for (int j = 0; j < HH; ++j) {
            wreg[j]        = W_hh0[i * HH + j];
            wreg[HH + j]   = W_hh0[(HH + i) * HH + j];
            wreg[2*HH + j] = W_hh0[(2*HH + i) * HH + j];
        }
        br = b_hh0[i]; bz = b_hh0[HH + i]; bn = b_hh0[2*HH + i];
        hprev = h0in[(b * 2 + 0) * HH + i];
        s_h0[3][i] = hprev;                       // prime slot for s0-1 = -1
    } else if (w == 1 && i < HH) {                // layer-0 input weights
#pragma unroll
        for (int c = 0; c < CC; ++c) {
            wreg[c]        = W_ih0[i * CC + c];
            wreg[CC + c]   = W_ih0[(HH + i) * CC + c];
            wreg[2*CC + c] = W_ih0[(2*HH + i) * CC + c];
        }
        br = b_ih0[i]; bz = b_ih0[HH + i]; bn = b_ih0[2*HH + i];
    } else if (w == 2 && i < HH) {                // layer-1 input weights
#pragma unroll
        for (int j = 0; j < HH; ++j) {
            wreg[j]        = W_ih1[i * HH + j];
            wreg[HH + j]   = W_ih1[(HH + i) * HH + j];
            wreg[2*HH + j] = W_ih1[(2*HH + i) * HH + j];
        }
        br = b_ih1[i]; bz = b_ih1[HH + i]; bn = b_ih1[2*HH + i];
    } else if (w == 3 && i < HH) {                // layer-1 recurrent weights
#pragma unroll
        for (int j = 0; j < HH; ++j) {
            wreg[j]        = W_hh1[i * HH + j];
            wreg[HH + j]   = W_hh1[(HH + i) * HH + j];
            wreg[2*HH + j] = W_hh1[(2*HH + i) * HH + j];
        }
        br = b_hh1[i]; bz = b_hh1[HH + i]; bn = b_hh1[2*HH + i];
        hprev = h0in[(b * 2 + 1) * HH + i];
        wo = W_o[i]; bo = b_o[0];
        s_h1[3][i] = hprev;                       // prime slot for s3-1 = -1
    }

    // Prime x chunk 0 (512 floats = 128 float4) cooperatively
    if (tid < 128)
        ((float4*)&s_x[0][0][0])[tid] = ((const float4*)xb)[tid];
    __syncthreads();

    // ---- main pipeline loop --------------------------------------------------
    for (int t = 0; t < TT + 3; ++t) {
        if (w == 1) {
            if (t < TT && i < HH) {
                // gx0[t] = W_ih0 . x[t] + b_ih0
                const float2* xp = (const float2*)&s_x[(t >> 5) & 3][t & 31][0];
                float r0 = br, z0 = bz, n0 = bn, r1 = 0.f, z1 = 0.f, n1 = 0.f;
#pragma unroll
                for (int c = 0; c < CC / 2; ++c) {
                    float2 xv = xp[c];
                    r0 = fmaf(wreg[2*c],        xv.x, r0);
                    r1 = fmaf(wreg[2*c + 1],    xv.y, r1);
                    z0 = fmaf(wreg[CC + 2*c],   xv.x, z0);
                    z1 = fmaf(wreg[CC + 2*c+1], xv.y, z1);
                    n0 = fmaf(wreg[2*CC + 2*c],   xv.x, n0);
                    n1 = fmaf(wreg[2*CC + 2*c+1], xv.y, n1);
                }
                const int s = t & 3;
                s_gx0[s][i]        = r0 + r1;
                s_gx0[s][HH + i]   = z0 + z1;
                s_gx0[s][2*HH + i] = n0 + n1;
            }
        } else if (w == 0) {
            const int s0 = t - 1;
            if (s0 >= 0 && s0 < TT && i < HH) {
                const int s = s0 & 3, sp = (s0 - 1) & 3;
                const float2* hp = (const float2*)&s_h0[sp][0];
                float r0 = br, z0 = bz, n0 = bn, r1 = 0.f, z1 = 0.f, n1 = 0.f;
#pragma unroll
                for (int j = 0; j < HH / 2; ++j) {
                    float2 hv = hp[j];
                    r0 = fmaf(wreg[2*j],          hv.x, r0);
                    r1 = fmaf(wreg[2*j + 1],      hv.y, r1);
                    z0 = fmaf(wreg[HH + 2*j],     hv.x, z0);
                    z1 = fmaf(wreg[HH + 2*j + 1], hv.y, z1);
                    n0 = fmaf(wreg[2*HH + 2*j],     hv.x, n0);
                    n1 = fmaf(wreg[2*HH + 2*j + 1], hv.y, n1);
                }
                const float ghr = r0 + r1, ghz = z0 + z1, ghn = n0 + n1;
                const float rr = sigf(s_gx0[s][i] + ghr);
                const float zz = sigf(s_gx0[s][HH + i] + ghz);
                const float nn = tanhf_(fmaf(rr, ghn, s_gx0[s][2*HH + i]));
                hprev = nn + zz * (hprev - nn);
                s_h0[s][i] = hprev;
            }
        } else if (w == 2) {
            const int s2 = t - 2;
            if (s2 >= 0 && s2 < TT && i < HH) {
                // gx1[s2] = W_ih1 . h0[s2] + b_ih1
                const int s = s2 & 3;
                const float2* hp = (const float2*)&s_h0[s][0];
                float r0 = br, z0 = bz, n0 = bn, r1 = 0.f, z1 = 0.f, n1 = 0.f;
#pragma unroll
                for (int j = 0; j < HH / 2; ++j) {
                    float2 hv = hp[j];
                    r0 = fmaf(wreg[2*j],          hv.x, r0);
                    r1 = fmaf(wreg[2*j + 1],      hv.y, r1);
                    z0 = fmaf(wreg[HH + 2*j],     hv.x, z0);
                    z1 = fmaf(wreg[HH + 2*j + 1], hv.y, z1);
                    n0 = fmaf(wreg[2*HH + 2*j],     hv.x, n0);
                    n1 = fmaf(wreg[2*HH + 2*j + 1], hv.y, n1);
                }
                s_gx1[s][i]        = r0 + r1;
                s_gx1[s][HH + i]   = z0 + z1;
                s_gx1[s][2*HH + i] = n0 + n1;
            }
        } else if (w == 3) {
            const int s3 = t - 3;
            if (s3 >= 0 && i < HH) {
                const int s = s3 & 3, sp = (s3 - 1) & 3;
                const float2* hp = (const float2*)&s_h1[sp][0];
                float r0 = br, z0 = bz, n0 = bn, r1 = 0.f, z1 = 0.f, n1 = 0.f;
#pragma unroll
                for (int j = 0; j < HH / 2; ++j) {
                    float2 hv = hp[j];
                    r0 = fmaf(wreg[2*j],          hv.x, r0);
                    r1 = fmaf(wreg[2*j + 1],      hv.y, r1);
                    z0 = fmaf(wreg[HH + 2*j],     hv.x, z0);
                    z1 = fmaf(wreg[HH + 2*j + 1], hv.y, z1);
                    n0 = fmaf(wreg[2*HH + 2*j],     hv.x, n0);
                    n1 = fmaf(wreg[2*HH + 2*j + 1], hv.y, n1);
                }
                const float ghr = r0 + r1, ghz = z0 + z1, ghn = n0 + n1;
                const float rr = sigf(s_gx1[s][i] + ghr);
                const float zz = sigf(s_gx1[s][HH + i] + ghz);
                const float nn = tanhf_(fmaf(rr, ghn, s_gx1[s][2*HH + i]));
                hprev = nn + zz * (hprev - nn);
                s_h1[s][i] = hprev;

                // o[b, s3] = dot(h1, W_o) + b_o  (warp reduce over 20 lanes)
                float v = hprev * wo;
                float u = __shfl_down_sync(MASK, v, 16);
                if (i < 4) v += u;
                v += __shfl_down_sync(MASK, v, 8);
                v += __shfl_down_sync(MASK, v, 4);
                v += __shfl_down_sync(MASK, v, 2);
                v += __shfl_down_sync(MASK, v, 1);
                if (i == 0) out[(size_t)b * TT + s3] = v + bo;
            }
        } else { // w == 4: DMA warp, prefetch next x chunk 32 steps ahead
            if ((t & (CHUNK - 1)) == 0) {
                const int c = (t >> 5) + 1;
                if (c < NCHUNK) {
                    const float4* src = (const float4*)(xb + (size_t)c * CHUNK * CC);
                    float4* dst = (float4*)&s_x[c & 3][0][0];
                    float4 v0 = src[i];
                    float4 v1 = src[i + 32];
                    float4 v2 = src[i + 64];
                    float4 v3 = src[i + 96];
                    dst[i]      = v0;
                    dst[i + 32] = v1;
                    dst[i + 64] = v2;
                    dst[i + 96] = v3;
                }
            }
        }
        __syncthreads();
    }

    // Final hidden states: h_n[b, layer, i]
    if (w == 0 && i < HH) out[(size_t)BB * TT + (b * 2 + 0) * HH + i] = hprev;
    if (w == 3 && i < HH) out[(size_t)BB * TT + (b * 2 + 1) * HH + i] = hprev;
}

// ---------------------------------------------------------------------------
extern "C" void kernel_launch(void* const* d_in, const int* in_sizes, int n_in,
                              void* d_out, int out_size) {
    const float* x     = (const float*)d_in[0];
    const float* h0    = (const float*)d_in[1];
    const float* W_ih0 = (const float*)d_in[2];
    const float* W_hh0 = (const float*)d_in[3];
    const float* b_ih0 = (const float*)d_in[4];
    const float* b_hh0 = (const float*)d_in[5];
    const float* W_ih1 = (const float*)d_in[6];
    const float* W_hh1 = (const float*)d_in[7];
    const float* b_ih1 = (const float*)d_in[8];
    const float* b_hh1 = (const float*)d_in[9];
    const float* W_o   = (const float*)d_in[10];
    const float* b_o   = (const float*)d_in[11];

    fused_gru_kernel<<<BB, 160>>>(x, h0, W_ih0, W_hh0, b_ih0, b_hh0,
                                  W_ih1, W_hh1, b_ih1, b_hh1, W_o, b_o,
                                  (float*)d_out);
}

// round 3
// speedup vs baseline: 9.2278x; 2.2400x over previous
#include <cuda_runtime.h>

// Fixed problem shape
#define BB 256
#define TT 4096
#define CC 16
#define HH 20
#define GG 60
#define K  16             // steps per chunk
#define NC (TT / K)       // 256 chunks

typedef unsigned long long u64;

__device__ __forceinline__ u64 pack2(float a, float b) {
    u64 r; asm("mov.b64 %0,{%1,%2};" : "=l"(r) : "f"(a), "f"(b)); return r;
}
__device__ __forceinline__ void fma2(u64& d, u64 a, u64 b) {
    asm("fma.rn.f32x2 %0,%1,%2,%0;" : "+l"(d) : "l"(a), "l"(b));
}
__device__ __forceinline__ float hsum2(u64 v) {
    float x, y; asm("mov.b64 {%0,%1},%2;" : "=f"(x), "=f"(y) : "l"(v)); return x + y;
}
__device__ __forceinline__ float tanha(float x) {
    float y; asm("tanh.approx.f32 %0,%1;" : "=f"(y) : "f"(x)); return y;
}
__device__ __forceinline__ float siga(float x) {
    return fmaf(tanha(x * 0.5f), 0.5f, 0.5f);
}

// ---------------------------------------------------------------------------
// Fused 2-layer GRU, chunked 4-stage pipeline, 2 batches per block (8 warps).
// Warp roles (heavy recurrence warps on distinct SMSPs = w%4):
//   w0: L0 batchA (SMSP0)   w1: GX0 A (S1)   w2: GX1 A (S2)   w3: L1 A (S3)
//   w4: GX0 B (S0)          w5: L0 B (S1)    w6: L1 B (S2)    w7: GX1 B (S3)
// Per outer iteration c (one __syncthreads at the end, same count all warps):
//   GX0: prefetch x chunk c+1 -> s_x; compute gx0 chunk c   -> s_gx0
//   L0 : GRU layer-0 for chunk c-1 (reads s_gx0)            -> s_h0
//   GX1: gx1 = W_ih1 . h0 for chunk c-2 (reads s_h0)        -> s_gx1
//   L1 : GRU layer-1 + output head for chunk c-3 (reads s_gx1) -> out
// Rings are 2 slots deep; writer and reader always touch opposite parities.
// ---------------------------------------------------------------------------
__global__ void __launch_bounds__(256, 1)
fused_gru_kernel(const float* __restrict__ x,      // [B,T,C]
                 const float* __restrict__ h0in,   // [B,2,H]
                 const float* __restrict__ W_ih0, const float* __restrict__ W_hh0,
                 const float* __restrict__ b_ih0, const float* __restrict__ b_hh0,
                 const float* __restrict__ W_ih1, const float* __restrict__ W_hh1,
                 const float* __restrict__ b_ih1, const float* __restrict__ b_hh1,
                 const float* __restrict__ W_o,   const float* __restrict__ b_o,
                 float* __restrict__ out)          // o[B*T] then h_n[B,2,H]
{
    __shared__ float s_x  [2][2][K][CC];   // [batch][slot][step][c]
    __shared__ float s_gx0[2][2][K][GG];
    __shared__ float s_gx1[2][2][K][GG];
    __shared__ float s_h0 [2][2][K][HH];

    const int tid = threadIdx.x;
    const int w   = tid >> 5;
    const int i   = tid & 31;
    const int bs  = (w >= 4);
    const int b   = blockIdx.x * 2 + bs;
    const bool act = (i < HH);
    const unsigned FULL = 0xFFFFFFFFu;

    const float* xb = x + (size_t)b * TT * CC;

    // ---- prime x chunk 0 (GX0 warps) ---------------------------------------
    if (w == 1 || w == 4) {
        const float4* src = (const float4*)xb;           // K*CC = 256 floats
        float4 v0 = src[i], v1 = src[i + 32];
        float4* dst = (float4*)&s_x[bs][0][0][0];
        dst[i] = v0; dst[i + 32] = v1;
    }
    __syncthreads();

    // =========================== role loops =================================
    if (w == 1 || w == 4) {
        // -------- GX0: gx0 = W_ih0 . x_t + b_ih0 --------
        u64 wp[24];                     // 3 gates x 8 packed pairs over c
        float br = 0.f, bz = 0.f, bn = 0.f;
#pragma unroll
        for (int g = 0; g < 3; ++g)
#pragma unroll
            for (int k = 0; k < 8; ++k)
                wp[g * 8 + k] = act ? pack2(W_ih0[(g * HH + i) * CC + 2 * k],
                                            W_ih0[(g * HH + i) * CC + 2 * k + 1])
                                    : pack2(0.f, 0.f);
        if (act) { br = b_ih0[i]; bz = b_ih0[HH + i]; bn = b_ih0[2 * HH + i]; }

        for (int c = 0; c < NC + 3; ++c) {
            if (c + 1 < NC) {           // prefetch x chunk c+1
                const float4* src = (const float4*)(xb + (size_t)(c + 1) * K * CC);
                float4 v0 = src[i], v1 = src[i + 32];
                float4* dst = (float4*)&s_x[bs][(c + 1) & 1][0][0];
                dst[i] = v0; dst[i + 32] = v1;
            }
            if (c < NC) {
                const float* xs = &s_x[bs][c & 1][0][0];
                float* go = &s_gx0[bs][c & 1][0][0];
#pragma unroll 4
                for (int s = 0; s < K; ++s) {
                    u64 ar = pack2(br, 0.f), az = pack2(bz, 0.f), an = pack2(bn, 0.f);
                    const float* xr = xs + s * CC;
#pragma unroll
                    for (int k = 0; k < 8; ++k) {
                        u64 xv = *(const u64*)(xr + 2 * k);      // LDS.64 broadcast
                        fma2(ar, wp[k], xv);
                        fma2(az, wp[8 + k], xv);
                        fma2(an, wp[16 + k], xv);
                    }
                    if (act) {
                        go[s * GG + i]          = hsum2(ar);
                        go[s * GG + HH + i]     = hsum2(az);
                        go[s * GG + 2 * HH + i] = hsum2(an);
                    }
                }
            }
            __syncthreads();
        }
    } else if (w == 2 || w == 7) {
        // -------- GX1: gx1 = W_ih1 . h0_t + b_ih1 --------
        u64 wp[30];
        float br = 0.f, bz = 0.f, bn = 0.f;
#pragma unroll
        for (int g = 0; g < 3; ++g)
#pragma unroll
            for (int k = 0; k < 10; ++k)
                wp[g * 10 + k] = act ? pack2(W_ih1[(g * HH + i) * HH + 2 * k],
                                             W_ih1[(g * HH + i) * HH + 2 * k + 1])
                                     : pack2(0.f, 0.f);
        if (act) { br = b_ih1[i]; bz = b_ih1[HH + i]; bn = b_ih1[2 * HH + i]; }

        for (int c = 0; c < NC + 3; ++c) {
            const int cc = c - 2;
            if (cc >= 0 && cc < NC) {
                const float* hr = &s_h0[bs][cc & 1][0][0];
                float* go = &s_gx1[bs][cc & 1][0][0];
#pragma unroll 4
                for (int s = 0; s < K; ++s) {
                    u64 ar = pack2(br, 0.f), az = pack2(bz, 0.f), an = pack2(bn, 0.f);
                    const float* hrow = hr + s * HH;
#pragma unroll
                    for (int k = 0; k < 10; ++k) {
                        u64 hv = *(const u64*)(hrow + 2 * k);    // LDS.64 broadcast
                        fma2(ar, wp[k], hv);
                        fma2(az, wp[10 + k], hv);
                        fma2(an, wp[20 + k], hv);
                    }
                    if (act) {
                        go[s * GG + i]          = hsum2(ar);
                        go[s * GG + HH + i]     = hsum2(az);
                        go[s * GG + 2 * HH + i] = hsum2(an);
                    }
                }
            }
            __syncthreads();
        }
    } else if (w == 0 || w == 5) {
        // -------- L0: layer-0 recurrence --------
        u64 wh[30];
        float br = 0.f, bz = 0.f, bn = 0.f, h = 0.f;
#pragma unroll
        for (int g = 0; g < 3; ++g)
#pragma unroll
            for (int k = 0; k < 10; ++k)
                wh[g * 10 + k] = act ? pack2(W_hh0[(g * HH + i) * HH + 2 * k],
                                             W_hh0[(g * HH + i) * HH + 2 * k + 1])
                                     : pack2(0.f, 0.f);
        if (act) {
            br = b_hh0[i]; bz = b_hh0[HH + i]; bn = b_hh0[2 * HH + i];
            h = h0in[(b * 2 + 0) * HH + i];
        }

        for (int c = 0; c < NC + 3; ++c) {
            const int cc = c - 1;
            if (cc >= 0 && cc < NC) {
                const float* gx = &s_gx0[bs][cc & 1][0][0];
                float* hw = &s_h0[bs][cc & 1][0][0];
#pragma unroll 2
                for (int s = 0; s < K; ++s) {
                    float gr = 0.f, gz = 0.f, gn = 0.f;
                    if (act) {
                        gr = gx[s * GG + i];
                        gz = gx[s * GG + HH + i];
                        gn = gx[s * GG + 2 * HH + i];
                    }
                    u64 hp[10];
#pragma unroll
                    for (int k = 0; k < 10; ++k)
                        hp[k] = pack2(__shfl_sync(FULL, h, 2 * k),
                                      __shfl_sync(FULL, h, 2 * k + 1));
                    u64 ar = pack2(br, 0.f), az = pack2(bz, 0.f), an = pack2(bn, 0.f);
#pragma unroll
                    for (int k = 0; k < 10; ++k) {
                        fma2(ar, wh[k],      hp[k]);
                        fma2(az, wh[10 + k], hp[k]);
                        fma2(an, wh[20 + k], hp[k]);
                    }
                    const float r = siga(gr + hsum2(ar));
                    const float z = siga(gz + hsum2(az));
                    const float n = tanha(fmaf(r, hsum2(an), gn));
                    h = fmaf(z, h - n, n);
                    if (act) hw[s * HH + i] = h;
                }
            }
            __syncthreads();
        }
        if (act) out[(size_t)BB * TT + (b * 2 + 0) * HH + i] = h;
    } else {
        // -------- L1: layer-1 recurrence + output head --------
        u64 wh[30];
        float br = 0.f, bz = 0.f, bn = 0.f, h = 0.f, wo = 0.f;
#pragma unroll
        for (int g = 0; g < 3; ++g)
#pragma unroll
            for (int k = 0; k < 10; ++k)
                wh[g * 10 + k] = act ? pack2(W_hh1[(g * HH + i) * HH + 2 * k],
                                             W_hh1[(g * HH + i) * HH + 2 * k + 1])
                                     : pack2(0.f, 0.f);
        if (act) {
            br = b_hh1[i]; bz = b_hh1[HH + i]; bn = b_hh1[2 * HH + i];
            h = h0in[(b * 2 + 1) * HH + i];
            wo = W_o[i];
        }
        const float bo = b_o[0];
        float* ob = out + (size_t)b * TT;

        for (int c = 0; c < NC + 3; ++c) {
            const int cc = c - 3;
            if (cc >= 0 && cc < NC) {
                const float* gx = &s_gx1[bs][cc & 1][0][0];
#pragma unroll 2
                for (int s = 0; s < K; ++s) {
                    float gr = 0.f, gz = 0.f, gn = 0.f;
                    if (act) {
                        gr = gx[s * GG + i];
                        gz = gx[s * GG + HH + i];
                        gn = gx[s * GG + 2 * HH + i];
                    }
                    u64 hp[10];
#pragma unroll
                    for (int k = 0; k < 10; ++k)
                        hp[k] = pack2(__shfl_sync(FULL, h, 2 * k),
                                      __shfl_sync(FULL, h, 2 * k + 1));
                    u64 ar = pack2(br, 0.f), az = pack2(bz, 0.f), an = pack2(bn, 0.f);
#pragma unroll
                    for (int k = 0; k < 10; ++k) {
                        fma2(ar, wh[k],      hp[k]);
                        fma2(az, wh[10 + k], hp[k]);
                        fma2(an, wh[20 + k], hp[k]);
                    }
                    const float r = siga(gr + hsum2(ar));
                    const float z = siga(gz + hsum2(az));
                    const float n = tanha(fmaf(r, hsum2(an), gn));
                    h = fmaf(z, h - n, n);

                    // output: o = dot(h, W_o) + b_o (lanes >= HH contribute 0)
                    float v = h * wo;
                    v += __shfl_down_sync(FULL, v, 16);
                    v += __shfl_down_sync(FULL, v, 8);
                    v += __shfl_down_sync(FULL, v, 4);
                    v += __shfl_down_sync(FULL, v, 2);
                    v += __shfl_down_sync(FULL, v, 1);
                    if (i == 0) ob[cc * K + s] = v + bo;
                }
            }
            __syncthreads();
        }
        if (act) out[(size_t)BB * TT + (b * 2 + 1) * HH + i] = h;
    }
}

// ---------------------------------------------------------------------------
extern "C" void kernel_launch(void* const* d_in, const int* in_sizes, int n_in,
                              void* d_out, int out_size) {
    const float* x     = (const float*)d_in[0];
    const float* h0    = (const float*)d_in[1];
    const float* W_ih0 = (const float*)d_in[2];
    const float* W_hh0 = (const float*)d_in[3];
    const float* b_ih0 = (const float*)d_in[4];
    const float* b_hh0 = (const float*)d_in[5];
    const float* W_ih1 = (const float*)d_in[6];
    const float* W_hh1 = (const float*)d_in[7];
    const float* b_ih1 = (const float*)d_in[8];
    const float* b_hh1 = (const float*)d_in[9];
    const float* W_o   = (const float*)d_in[10];
    const float* b_o   = (const float*)d_in[11];

    fused_gru_kernel<<<BB / 2, 256>>>(x, h0, W_ih0, W_hh0, b_ih0, b_hh0,
                                      W_ih1, W_hh1, b_ih1, b_hh1, W_o, b_o,
                                      (float*)d_out);
}